// round 10
// baseline (speedup 1.0000x reference)
#include <cuda_runtime.h>
#include <math.h>

#define MAX_N 100000
#define MAX_E 1600000
#define D 64
#define TWO_D 128
#define SCAN_B 512
#define MAXNB ((MAX_N + SCAN_B - 1) / SCAN_B)   // 196

// Scratch (static __device__ arrays — no allocations allowed)
__device__ float4 g_gate[MAX_N];                 // (low_dst, low_src, high_dst, high_src)
__device__ float  g_WrT[TWO_D * D];              // Wr transposed [k][j]
__device__ int    g_deg[MAX_N];
__device__ int    g_start[MAX_N];
__device__ int    g_cursor[MAX_N];
__device__ int    g_bsum[MAXNB + 1];
__device__ int    g_esrc[MAX_E];                 // dst-grouped src indices

// ---------------------------------------------------------------------------
// Gate projections: one warp per node. Fused: Wr transpose + deg zero.
// ---------------------------------------------------------------------------
__global__ void gate_kernel(const float* __restrict__ h,
                            const float* __restrict__ Wl,
                            const float* __restrict__ Wh,
                            const float* __restrict__ Wr,
                            int n)
{
    int gtid = blockIdx.x * blockDim.x + threadIdx.x;

    if (gtid < D * TWO_D) {
        int j = gtid >> 7;
        int k = gtid & 127;
        g_WrT[k * D + j] = Wr[gtid];
    }
    if (gtid < n) g_deg[gtid] = 0;

    int warp = gtid >> 5;
    int lane = threadIdx.x & 31;
    if (warp >= n) return;

    const float* hp = h + (size_t)warp * D;
    float a0 = hp[lane];
    float a1 = hp[lane + 32];

    float ld = a0 * Wl[lane]      + a1 * Wl[lane + 32];
    float ls = a0 * Wl[lane + 64] + a1 * Wl[lane + 96];
    float hd = a0 * Wh[lane]      + a1 * Wh[lane + 32];
    float hs = a0 * Wh[lane + 64] + a1 * Wh[lane + 96];

    #pragma unroll
    for (int off = 16; off; off >>= 1) {
        ld += __shfl_xor_sync(0xFFFFFFFFu, ld, off);
        ls += __shfl_xor_sync(0xFFFFFFFFu, ls, off);
        hd += __shfl_xor_sync(0xFFFFFFFFu, hd, off);
        hs += __shfl_xor_sync(0xFFFFFFFFu, hs, off);
    }
    if (lane == 0) g_gate[warp] = make_float4(ld, ls, hd, hs);
}

// ---------------------------------------------------------------------------
// Histogram of dst (vectorized int4 loads, fire-and-forget atomics).
// ---------------------------------------------------------------------------
__global__ void hist_kernel(const int* __restrict__ dst, int e)
{
    int i = blockIdx.x * blockDim.x + threadIdx.x;
    int e4 = e >> 2;
    if (i < e4) {
        int4 d4 = reinterpret_cast<const int4*>(dst)[i];
        atomicAdd(&g_deg[d4.x], 1);
        atomicAdd(&g_deg[d4.y], 1);
        atomicAdd(&g_deg[d4.z], 1);
        atomicAdd(&g_deg[d4.w], 1);
    }
    int t = e4 * 4 + i;
    if (i < (e & 3)) {
        atomicAdd(&g_deg[dst[t]], 1);
    }
}

// ---------------------------------------------------------------------------
// scan1: block-local exclusive scan via warp shuffles (512 thr = 16 warps).
// ---------------------------------------------------------------------------
__global__ void scan1_kernel(int n)
{
    __shared__ int swarp[16];
    int tid  = threadIdx.x;
    int lane = tid & 31;
    int wid  = tid >> 5;
    int i = blockIdx.x * SCAN_B + tid;
    int v = (i < n) ? g_deg[i] : 0;

    int x = v;
    #pragma unroll
    for (int off = 1; off < 32; off <<= 1) {
        int t = __shfl_up_sync(0xFFFFFFFFu, x, off);
        if (lane >= off) x += t;
    }
    if (lane == 31) swarp[wid] = x;
    __syncthreads();

    if (wid == 0) {
        int w = (lane < 16) ? swarp[lane] : 0;
        #pragma unroll
        for (int off = 1; off < 16; off <<= 1) {
            int t = __shfl_up_sync(0xFFFFFFFFu, w, off);
            if (lane >= off) w += t;
        }
        if (lane < 16) swarp[lane] = w;
    }
    __syncthreads();

    int wbase = (wid > 0) ? swarp[wid - 1] : 0;
    if (i < n) g_start[i] = wbase + x - v;
    if (tid == SCAN_B - 1) g_bsum[blockIdx.x] = wbase + x;
}

// ---------------------------------------------------------------------------
// scan3 (absorbs scan2): each block locally scans the <=196 block sums in
// shared, then applies the offset. 256 threads.
// ---------------------------------------------------------------------------
__global__ void scan3_kernel(int n, int nb)
{
    __shared__ int sb[MAXNB];
    __shared__ int swarp[8];
    int tid  = threadIdx.x;
    int lane = tid & 31;
    int wid  = tid >> 5;

    // local exclusive scan of g_bsum[0..nb) into sb
    int v = (tid < nb) ? g_bsum[tid] : 0;
    int x = v;
    #pragma unroll
    for (int off = 1; off < 32; off <<= 1) {
        int t = __shfl_up_sync(0xFFFFFFFFu, x, off);
        if (lane >= off) x += t;
    }
    if (lane == 31) swarp[wid] = x;
    __syncthreads();
    if (wid == 0) {
        int w = (lane < 8) ? swarp[lane] : 0;
        #pragma unroll
        for (int off = 1; off < 8; off <<= 1) {
            int t = __shfl_up_sync(0xFFFFFFFFu, w, off);
            if (lane >= off) w += t;
        }
        if (lane < 8) swarp[lane] = w;
    }
    __syncthreads();
    int wbase = (wid > 0) ? swarp[wid - 1] : 0;
    if (tid < nb) sb[tid] = wbase + x - v;       // exclusive block prefix
    __syncthreads();

    int i = blockIdx.x * blockDim.x + tid;
    if (i < n) {
        int s = g_start[i] + sb[i / SCAN_B];
        g_start[i] = s;
        g_cursor[i] = s;
    }
}

// ---------------------------------------------------------------------------
// Fill: permute src into dst-grouped CSR order (one thread per edge).
// ---------------------------------------------------------------------------
__global__ void fill_kernel(const int* __restrict__ src,
                            const int* __restrict__ dst,
                            int e)
{
    int i = blockIdx.x * blockDim.x + threadIdx.x;
    if (i >= e) return;
    int pos = atomicAdd(&g_cursor[dst[i]], 1);
    g_esrc[pos] = src[i];
}

// ---------------------------------------------------------------------------
// FUSED gather + output projection. Persistent: grid fixed, each warp loops
// over nodes. Per node: accumulate z (registers) from CSR edges, stash in
// shared, then epilogue out[node] = z @ WrT + br from block-resident sW.
// smem: sW 32KB + sZ 4KB.
// ---------------------------------------------------------------------------
__global__ void __launch_bounds__(256) gather_out_kernel(
    const float* __restrict__ h,
    const float* __restrict__ dnorm,
    const float* __restrict__ bl,
    const float* __restrict__ bh,
    const float* __restrict__ br,
    float* __restrict__ out,
    int n, int total_warps)
{
    __shared__ __align__(16) float sW[TWO_D * D];       // [k][j]
    __shared__ __align__(16) float sZ[8 * TWO_D];       // per-warp z row

    int tid  = threadIdx.x;
    int lane = tid & 31;
    int wib  = tid >> 5;                                 // warp in block

    // stage WrT once per block
    {
        const float4* Wg = reinterpret_cast<const float4*>(g_WrT);
        float4* Ws = reinterpret_cast<float4*>(sW);
        #pragma unroll
        for (int i = tid; i < (TWO_D * D) / 4; i += 256)
            Ws[i] = Wg[i];
    }
    __syncthreads();

    int gwarp = blockIdx.x * 8 + wib;
    float bl0 = bl[0];
    float bh0 = bh[0];
    float2 brv = reinterpret_cast<const float2*>(br)[lane];
    float* zrow = sZ + wib * TWO_D;

    for (int node = gwarp; node < n; node += total_warps) {
        int start = g_start[node];
        int deg   = g_deg[node];
        int end   = start + deg;

        float4 gt  = g_gate[node];
        float dn_t = dnorm[node];

        float zl0 = 0.f, zl1 = 0.f, zh0 = 0.f, zh1 = 0.f;

        for (int base = start; base < end; base += 32) {
            int my = base + lane;
            int msrc = 0;
            float mel = 0.f, meh = 0.f;
            if (my < end) {
                msrc = g_esrc[my];
                float4 gs = g_gate[msrc];
                float xl = gt.x + gs.y + bl0;
                float xh = gt.z + gs.w + bh0;
                float gl =  tanhf(xl > 0.f ? xl : -0.5f * xl);
                float gh = -tanhf(xh > 0.f ? xh : -0.5f * xh);
                float dd = dn_t * dnorm[msrc];
                mel = gl * dd;
                meh = gh * dd;
            }
            int cnt = min(32, end - base);

            int i = 0;
            for (; i + 4 <= cnt; i += 4) {
                int s0 = __shfl_sync(0xFFFFFFFFu, msrc, i);
                int s1 = __shfl_sync(0xFFFFFFFFu, msrc, i + 1);
                int s2 = __shfl_sync(0xFFFFFFFFu, msrc, i + 2);
                int s3 = __shfl_sync(0xFFFFFFFFu, msrc, i + 3);
                float cl0 = __shfl_sync(0xFFFFFFFFu, mel, i);
                float ch0 = __shfl_sync(0xFFFFFFFFu, meh, i);
                float cl1 = __shfl_sync(0xFFFFFFFFu, mel, i + 1);
                float ch1 = __shfl_sync(0xFFFFFFFFu, meh, i + 1);
                float cl2 = __shfl_sync(0xFFFFFFFFu, mel, i + 2);
                float ch2 = __shfl_sync(0xFFFFFFFFu, meh, i + 2);
                float cl3 = __shfl_sync(0xFFFFFFFFu, mel, i + 3);
                float ch3 = __shfl_sync(0xFFFFFFFFu, meh, i + 3);

                const float* p0 = h + (size_t)s0 * D;
                const float* p1 = h + (size_t)s1 * D;
                const float* p2 = h + (size_t)s2 * D;
                const float* p3 = h + (size_t)s3 * D;
                float a0 = p0[lane], b0 = p0[lane + 32];
                float a1 = p1[lane], b1 = p1[lane + 32];
                float a2 = p2[lane], b2 = p2[lane + 32];
                float a3 = p3[lane], b3 = p3[lane + 32];

                zl0 = fmaf(a0, cl0, zl0); zl1 = fmaf(b0, cl0, zl1);
                zh0 = fmaf(a0, ch0, zh0); zh1 = fmaf(b0, ch0, zh1);
                zl0 = fmaf(a1, cl1, zl0); zl1 = fmaf(b1, cl1, zl1);
                zh0 = fmaf(a1, ch1, zh0); zh1 = fmaf(b1, ch1, zh1);
                zl0 = fmaf(a2, cl2, zl0); zl1 = fmaf(b2, cl2, zl1);
                zh0 = fmaf(a2, ch2, zh0); zh1 = fmaf(b2, ch2, zh1);
                zl0 = fmaf(a3, cl3, zl0); zl1 = fmaf(b3, cl3, zl1);
                zh0 = fmaf(a3, ch3, zh0); zh1 = fmaf(b3, ch3, zh1);
            }
            for (; i < cnt; i++) {
                int s0 = __shfl_sync(0xFFFFFFFFu, msrc, i);
                float cl = __shfl_sync(0xFFFFFFFFu, mel, i);
                float ch = __shfl_sync(0xFFFFFFFFu, meh, i);
                const float* p0 = h + (size_t)s0 * D;
                float a0 = p0[lane], b0 = p0[lane + 32];
                zl0 = fmaf(a0, cl, zl0); zl1 = fmaf(b0, cl, zl1);
                zh0 = fmaf(a0, ch, zh0); zh1 = fmaf(b0, ch, zh1);
            }
        }

        // epilogue: out[node] = z @ WrT + br
        zrow[lane]      = zl0;
        zrow[lane + 32] = zl1;
        zrow[lane + 64] = zh0;
        zrow[lane + 96] = zh1;
        __syncwarp();

        float2 acc = make_float2(0.f, 0.f);
        const float2* wp = reinterpret_cast<const float2*>(sW);
        const float4* z4 = reinterpret_cast<const float4*>(zrow);
        #pragma unroll 8
        for (int kq = 0; kq < TWO_D / 4; kq++) {
            float4 zk = z4[kq];                       // broadcast (all lanes same)
            float2 w0 = wp[(kq * 4 + 0) * 32 + lane];
            float2 w1 = wp[(kq * 4 + 1) * 32 + lane];
            float2 w2 = wp[(kq * 4 + 2) * 32 + lane];
            float2 w3 = wp[(kq * 4 + 3) * 32 + lane];
            acc.x = fmaf(zk.x, w0.x, acc.x); acc.y = fmaf(zk.x, w0.y, acc.y);
            acc.x = fmaf(zk.y, w1.x, acc.x); acc.y = fmaf(zk.y, w1.y, acc.y);
            acc.x = fmaf(zk.z, w2.x, acc.x); acc.y = fmaf(zk.z, w2.y, acc.y);
            acc.x = fmaf(zk.w, w3.x, acc.x); acc.y = fmaf(zk.w, w3.y, acc.y);
        }
        acc.x += brv.x;
        acc.y += brv.y;
        *reinterpret_cast<float2*>(out + (size_t)node * D + lane * 2) = acc;
        __syncwarp();   // protect zrow before next node overwrites
    }
}

// ---------------------------------------------------------------------------
extern "C" void kernel_launch(void* const* d_in, const int* in_sizes, int n_in,
                              void* d_out, int out_size)
{
    const float* h   = (const float*)d_in[0];
    const float* dn  = (const float*)d_in[1];
    const int*   src = (const int*)  d_in[2];
    const int*   dst = (const int*)  d_in[3];
    const float* Wl  = (const float*)d_in[4];
    const float* bl  = (const float*)d_in[5];
    const float* Wh  = (const float*)d_in[6];
    const float* bh  = (const float*)d_in[7];
    const float* Wr  = (const float*)d_in[8];
    const float* br  = (const float*)d_in[9];
    float* out = (float*)d_out;

    int n = in_sizes[0] / D;      // nodes
    int e = in_sizes[2];          // edges
    int nb = (n + SCAN_B - 1) / SCAN_B;

    gate_kernel<<<(n * 32 + 255) / 256, 256>>>(h, Wl, Wh, Wr, n);

    hist_kernel<<<((e >> 2) + 255) / 256, 256>>>(dst, e);
    scan1_kernel<<<nb, SCAN_B>>>(n);
    scan3_kernel<<<(n + 255) / 256, 256>>>(n, nb);
    fill_kernel<<<(e + 255) / 256, 256>>>(src, dst, e);

    // Fused gather + projection: persistent grid (6 blocks/SM by smem, 148 SMs)
    const int blocks = 888;
    const int total_warps = blocks * 8;
    gather_out_kernel<<<blocks, 256>>>(h, dn, bl, bh, br, out, n, total_warps);
}

// round 11
// speedup vs baseline: 1.3158x; 1.3158x over previous
#include <cuda_runtime.h>
#include <math.h>

#define MAX_N 100000
#define MAX_E 1600000
#define D 64
#define TWO_D 128
#define NB 64
#define SCAN_B 512
#define MAXNB ((MAX_N + SCAN_B - 1) / SCAN_B)   // 196

// Scratch (static __device__ arrays — no allocations allowed)
__device__ float4 g_srcv[MAX_N];                 // (low_src, high_src, dnorm, 0) — gathered per edge
__device__ float4 g_dstv[MAX_N];                 // (low_dst, high_dst, dnorm, 0) — broadcast per node
__device__ float  g_z[(size_t)MAX_N * TWO_D];    // [N, 2D] aggregation (z_low | z_high)
__device__ float  g_WrT[TWO_D * D];              // Wr transposed [k][j]
__device__ int    g_deg[MAX_N];
__device__ int    g_start[MAX_N];
__device__ int    g_cursor[MAX_N];
__device__ int    g_bsum[MAXNB + 1];
__device__ int    g_esrc[MAX_E];                 // dst-grouped src indices

// ---------------------------------------------------------------------------
// Gate projections: one warp per node. Fused: Wr transpose + deg zero.
// Writes packed src-side and dst-side per-node vectors (dnorm folded in).
// ---------------------------------------------------------------------------
__global__ void gate_kernel(const float* __restrict__ h,
                            const float* __restrict__ dnorm,
                            const float* __restrict__ Wl,
                            const float* __restrict__ Wh,
                            const float* __restrict__ Wr,
                            int n)
{
    int gtid = blockIdx.x * blockDim.x + threadIdx.x;

    if (gtid < D * TWO_D) {
        int j = gtid >> 7;
        int k = gtid & 127;
        g_WrT[k * D + j] = Wr[gtid];
    }
    if (gtid < n) g_deg[gtid] = 0;

    int warp = gtid >> 5;
    int lane = threadIdx.x & 31;
    if (warp >= n) return;

    const float* hp = h + (size_t)warp * D;
    float a0 = hp[lane];
    float a1 = hp[lane + 32];

    float ld = a0 * Wl[lane]      + a1 * Wl[lane + 32];
    float ls = a0 * Wl[lane + 64] + a1 * Wl[lane + 96];
    float hd = a0 * Wh[lane]      + a1 * Wh[lane + 32];
    float hs = a0 * Wh[lane + 64] + a1 * Wh[lane + 96];

    #pragma unroll
    for (int off = 16; off; off >>= 1) {
        ld += __shfl_xor_sync(0xFFFFFFFFu, ld, off);
        ls += __shfl_xor_sync(0xFFFFFFFFu, ls, off);
        hd += __shfl_xor_sync(0xFFFFFFFFu, hd, off);
        hs += __shfl_xor_sync(0xFFFFFFFFu, hs, off);
    }
    if (lane == 0) {
        float dn = dnorm[warp];
        g_srcv[warp] = make_float4(ls, hs, dn, 0.f);
        g_dstv[warp] = make_float4(ld, hd, dn, 0.f);
    }
}

// ---------------------------------------------------------------------------
// Histogram of dst (vectorized int4 loads, fire-and-forget atomics).
// ---------------------------------------------------------------------------
__global__ void hist_kernel(const int* __restrict__ dst, int e)
{
    int i = blockIdx.x * blockDim.x + threadIdx.x;
    int e4 = e >> 2;
    if (i < e4) {
        int4 d4 = reinterpret_cast<const int4*>(dst)[i];
        atomicAdd(&g_deg[d4.x], 1);
        atomicAdd(&g_deg[d4.y], 1);
        atomicAdd(&g_deg[d4.z], 1);
        atomicAdd(&g_deg[d4.w], 1);
    }
    int t = e4 * 4 + i;
    if (i < (e & 3)) {
        atomicAdd(&g_deg[dst[t]], 1);
    }
}

// ---------------------------------------------------------------------------
// scan1: block-local exclusive scan via warp shuffles (512 thr = 16 warps).
// ---------------------------------------------------------------------------
__global__ void scan1_kernel(int n)
{
    __shared__ int swarp[16];
    int tid  = threadIdx.x;
    int lane = tid & 31;
    int wid  = tid >> 5;
    int i = blockIdx.x * SCAN_B + tid;
    int v = (i < n) ? g_deg[i] : 0;

    int x = v;
    #pragma unroll
    for (int off = 1; off < 32; off <<= 1) {
        int t = __shfl_up_sync(0xFFFFFFFFu, x, off);
        if (lane >= off) x += t;
    }
    if (lane == 31) swarp[wid] = x;
    __syncthreads();

    if (wid == 0) {
        int w = (lane < 16) ? swarp[lane] : 0;
        #pragma unroll
        for (int off = 1; off < 16; off <<= 1) {
            int t = __shfl_up_sync(0xFFFFFFFFu, w, off);
            if (lane >= off) w += t;
        }
        if (lane < 16) swarp[lane] = w;
    }
    __syncthreads();

    int wbase = (wid > 0) ? swarp[wid - 1] : 0;
    if (i < n) g_start[i] = wbase + x - v;
    if (tid == SCAN_B - 1) g_bsum[blockIdx.x] = wbase + x;
}

// ---------------------------------------------------------------------------
// scan3 (absorbs scan2): each block locally scans the <=196 block sums.
// ---------------------------------------------------------------------------
__global__ void scan3_kernel(int n, int nb)
{
    __shared__ int sb[MAXNB];
    __shared__ int swarp[8];
    int tid  = threadIdx.x;
    int lane = tid & 31;
    int wid  = tid >> 5;

    int v = (tid < nb) ? g_bsum[tid] : 0;
    int x = v;
    #pragma unroll
    for (int off = 1; off < 32; off <<= 1) {
        int t = __shfl_up_sync(0xFFFFFFFFu, x, off);
        if (lane >= off) x += t;
    }
    if (lane == 31) swarp[wid] = x;
    __syncthreads();
    if (wid == 0) {
        int w = (lane < 8) ? swarp[lane] : 0;
        #pragma unroll
        for (int off = 1; off < 8; off <<= 1) {
            int t = __shfl_up_sync(0xFFFFFFFFu, w, off);
            if (lane >= off) w += t;
        }
        if (lane < 8) swarp[lane] = w;
    }
    __syncthreads();
    int wbase = (wid > 0) ? swarp[wid - 1] : 0;
    if (tid < nb) sb[tid] = wbase + x - v;
    __syncthreads();

    int i = blockIdx.x * blockDim.x + tid;
    if (i < n) {
        int s = g_start[i] + sb[i / SCAN_B];
        g_start[i] = s;
        g_cursor[i] = s;
    }
}

// ---------------------------------------------------------------------------
// Fill: permute src into dst-grouped CSR order (one thread per edge).
// ---------------------------------------------------------------------------
__global__ void fill_kernel(const int* __restrict__ src,
                            const int* __restrict__ dst,
                            int e)
{
    int i = blockIdx.x * blockDim.x + threadIdx.x;
    if (i >= e) return;
    int pos = atomicAdd(&g_cursor[dst[i]], 1);
    g_esrc[pos] = src[i];
}

// ---------------------------------------------------------------------------
// Gather-aggregate: one warp per node, strided lanes, unroll 4.
// Per-edge coef now needs ONE packed LDG.128 (g_srcv) — dnorm gather removed.
// ---------------------------------------------------------------------------
__global__ void gather_kernel(const float* __restrict__ h,
                              const float* __restrict__ bl,
                              const float* __restrict__ bh,
                              int n)
{
    int warp = (blockIdx.x * blockDim.x + threadIdx.x) >> 5;
    int lane = threadIdx.x & 31;
    if (warp >= n) return;

    int start = g_start[warp];
    int deg   = g_deg[warp];
    int end   = start + deg;

    float4 dv  = g_dstv[warp];            // (ld, hd, dn_t)
    float bl0  = bl[0];
    float bh0  = bh[0];
    float xl_base = dv.x + bl0;
    float xh_base = dv.y + bh0;
    float dn_t = dv.z;

    float zl0 = 0.f, zl1 = 0.f, zh0 = 0.f, zh1 = 0.f;

    for (int base = start; base < end; base += 32) {
        int my = base + lane;
        int msrc = 0;
        float mel = 0.f, meh = 0.f;
        if (my < end) {
            msrc = g_esrc[my];
            float4 sv = g_srcv[msrc];     // (ls, hs, dn_s)
            float xl = xl_base + sv.x;
            float xh = xh_base + sv.y;
            float gl =  tanhf(xl > 0.f ? xl : -0.5f * xl);
            float gh = -tanhf(xh > 0.f ? xh : -0.5f * xh);
            float dd = dn_t * sv.z;
            mel = gl * dd;
            meh = gh * dd;
        }
        int cnt = min(32, end - base);

        int i = 0;
        for (; i + 4 <= cnt; i += 4) {
            int s0 = __shfl_sync(0xFFFFFFFFu, msrc, i);
            int s1 = __shfl_sync(0xFFFFFFFFu, msrc, i + 1);
            int s2 = __shfl_sync(0xFFFFFFFFu, msrc, i + 2);
            int s3 = __shfl_sync(0xFFFFFFFFu, msrc, i + 3);
            float cl0 = __shfl_sync(0xFFFFFFFFu, mel, i);
            float ch0 = __shfl_sync(0xFFFFFFFFu, meh, i);
            float cl1 = __shfl_sync(0xFFFFFFFFu, mel, i + 1);
            float ch1 = __shfl_sync(0xFFFFFFFFu, meh, i + 1);
            float cl2 = __shfl_sync(0xFFFFFFFFu, mel, i + 2);
            float ch2 = __shfl_sync(0xFFFFFFFFu, meh, i + 2);
            float cl3 = __shfl_sync(0xFFFFFFFFu, mel, i + 3);
            float ch3 = __shfl_sync(0xFFFFFFFFu, meh, i + 3);

            const float* p0 = h + (size_t)s0 * D;
            const float* p1 = h + (size_t)s1 * D;
            const float* p2 = h + (size_t)s2 * D;
            const float* p3 = h + (size_t)s3 * D;
            float a0 = p0[lane], b0 = p0[lane + 32];
            float a1 = p1[lane], b1 = p1[lane + 32];
            float a2 = p2[lane], b2 = p2[lane + 32];
            float a3 = p3[lane], b3 = p3[lane + 32];

            zl0 = fmaf(a0, cl0, zl0); zl1 = fmaf(b0, cl0, zl1);
            zh0 = fmaf(a0, ch0, zh0); zh1 = fmaf(b0, ch0, zh1);
            zl0 = fmaf(a1, cl1, zl0); zl1 = fmaf(b1, cl1, zl1);
            zh0 = fmaf(a1, ch1, zh0); zh1 = fmaf(b1, ch1, zh1);
            zl0 = fmaf(a2, cl2, zl0); zl1 = fmaf(b2, cl2, zl1);
            zh0 = fmaf(a2, ch2, zh0); zh1 = fmaf(b2, ch2, zh1);
            zl0 = fmaf(a3, cl3, zl0); zl1 = fmaf(b3, cl3, zl1);
            zh0 = fmaf(a3, ch3, zh0); zh1 = fmaf(b3, ch3, zh1);
        }
        for (; i < cnt; i++) {
            int s0 = __shfl_sync(0xFFFFFFFFu, msrc, i);
            float cl = __shfl_sync(0xFFFFFFFFu, mel, i);
            float ch = __shfl_sync(0xFFFFFFFFu, meh, i);
            const float* p0 = h + (size_t)s0 * D;
            float a0 = p0[lane], b0 = p0[lane + 32];
            zl0 = fmaf(a0, cl, zl0); zl1 = fmaf(b0, cl, zl1);
            zh0 = fmaf(a0, ch, zh0); zh1 = fmaf(b0, ch, zh1);
        }
    }

    float* z = g_z + (size_t)warp * TWO_D;
    z[lane]      = zl0;
    z[lane + 32] = zl1;
    z[lane + 64] = zh0;
    z[lane + 96] = zh1;
}

// ---------------------------------------------------------------------------
// Output projection, register-blocked 4x4 (R5/R9 scalar version).
// ---------------------------------------------------------------------------
__global__ void __launch_bounds__(256) out_kernel(const float* __restrict__ br,
                                                  float* __restrict__ out,
                                                  int n)
{
    __shared__ float sW[TWO_D * D];
    __shared__ float sZ[NB * TWO_D];

    int tid = threadIdx.x;
    int node0 = blockIdx.x * NB;

    {
        const float4* Wg = reinterpret_cast<const float4*>(g_WrT);
        float4* Ws = reinterpret_cast<float4*>(sW);
        #pragma unroll
        for (int i = tid; i < (TWO_D * D) / 4; i += 256)
            Ws[i] = Wg[i];
    }
    {
        const float4* Zg = reinterpret_cast<const float4*>(g_z) + (size_t)node0 * (TWO_D / 4);
        float4* Zs = reinterpret_cast<float4*>(sZ);
        #pragma unroll
        for (int i = tid; i < NB * (TWO_D / 4); i += 256) {
            int node = node0 + i / (TWO_D / 4);
            Zs[i] = (node < n) ? Zg[i] : make_float4(0.f, 0.f, 0.f, 0.f);
        }
    }
    __syncthreads();

    int jg = tid & 15;
    int ng = tid >> 4;

    float acc[4][4];
    #pragma unroll
    for (int i = 0; i < 4; i++)
        #pragma unroll
        for (int jj = 0; jj < 4; jj++)
            acc[i][jj] = 0.f;

    const float4* sW4 = reinterpret_cast<const float4*>(sW);
    const float* zbase = sZ + ng * 4 * TWO_D;

    #pragma unroll 4
    for (int k = 0; k < TWO_D; k++) {
        float4 w = sW4[k * (D / 4) + jg];
        float z0 = zbase[0 * TWO_D + k];
        float z1 = zbase[1 * TWO_D + k];
        float z2 = zbase[2 * TWO_D + k];
        float z3 = zbase[3 * TWO_D + k];
        acc[0][0] = fmaf(z0, w.x, acc[0][0]); acc[0][1] = fmaf(z0, w.y, acc[0][1]);
        acc[0][2] = fmaf(z0, w.z, acc[0][2]); acc[0][3] = fmaf(z0, w.w, acc[0][3]);
        acc[1][0] = fmaf(z1, w.x, acc[1][0]); acc[1][1] = fmaf(z1, w.y, acc[1][1]);
        acc[1][2] = fmaf(z1, w.z, acc[1][2]); acc[1][3] = fmaf(z1, w.w, acc[1][3]);
        acc[2][0] = fmaf(z2, w.x, acc[2][0]); acc[2][1] = fmaf(z2, w.y, acc[2][1]);
        acc[2][2] = fmaf(z2, w.z, acc[2][2]); acc[2][3] = fmaf(z2, w.w, acc[2][3]);
        acc[3][0] = fmaf(z3, w.x, acc[3][0]); acc[3][1] = fmaf(z3, w.y, acc[3][1]);
        acc[3][2] = fmaf(z3, w.z, acc[3][2]); acc[3][3] = fmaf(z3, w.w, acc[3][3]);
    }

    int j = jg * 4;
    float4 b4 = *reinterpret_cast<const float4*>(br + j);
    #pragma unroll
    for (int i = 0; i < 4; i++) {
        int node = node0 + ng * 4 + i;
        if (node < n) {
            float4 o;
            o.x = acc[i][0] + b4.x;
            o.y = acc[i][1] + b4.y;
            o.z = acc[i][2] + b4.z;
            o.w = acc[i][3] + b4.w;
            *reinterpret_cast<float4*>(out + (size_t)node * D + j) = o;
        }
    }
}

// ---------------------------------------------------------------------------
extern "C" void kernel_launch(void* const* d_in, const int* in_sizes, int n_in,
                              void* d_out, int out_size)
{
    const float* h   = (const float*)d_in[0];
    const float* dn  = (const float*)d_in[1];
    const int*   src = (const int*)  d_in[2];
    const int*   dst = (const int*)  d_in[3];
    const float* Wl  = (const float*)d_in[4];
    const float* bl  = (const float*)d_in[5];
    const float* Wh  = (const float*)d_in[6];
    const float* bh  = (const float*)d_in[7];
    const float* Wr  = (const float*)d_in[8];
    const float* br  = (const float*)d_in[9];
    float* out = (float*)d_out;

    int n = in_sizes[0] / D;      // nodes
    int e = in_sizes[2];          // edges
    int nb = (n + SCAN_B - 1) / SCAN_B;

    gate_kernel<<<(n * 32 + 255) / 256, 256>>>(h, dn, Wl, Wh, Wr, n);

    hist_kernel<<<((e >> 2) + 255) / 256, 256>>>(dst, e);
    scan1_kernel<<<nb, SCAN_B>>>(n);
    scan3_kernel<<<(n + 255) / 256, 256>>>(n, nb);
    fill_kernel<<<(e + 255) / 256, 256>>>(src, dst, e);

    gather_kernel<<<(int)(((size_t)n * 32 + 255) / 256), 256>>>(h, bl, bh, n);

    out_kernel<<<(n + NB - 1) / NB, 256>>>(br, out, n);
}